// round 9
// baseline (speedup 1.0000x reference)
#include <cuda_runtime.h>

#define B_ 8192
#define T_ 128
#define DT_ 0.01f
#define THREADS 128
#define ROWS 16
#define NBLK (B_ / ROWS)

// shared memory layout (float offsets)
// W1s rows: 0..17 dynamic inputs (e6, ed6, xi6); 18 = beta (×E); 19 = gamma (×nu); 20 = alpha (init)
#define OFF_W1    0          // [21][512]
#define OFF_XS    10752      // [2 pairs][2 buf][21 k][8 rows][2 dup]
#define OFF_PP    12096      // [2 pairs][112] partials
#define SMEM_FLOATS 12320
#define SMEM_BYTES (SMEM_FLOATS * 4)

typedef unsigned long long u64;

__device__ __forceinline__ u64 ffma2(u64 a, u64 b, u64 c) {
    u64 d; asm("fma.rn.f32x2 %0, %1, %2, %3;" : "=l"(d) : "l"(a), "l"(b), "l"(c));
    return d;
}
__device__ __forceinline__ u64 dup2(float x) {
    u64 d; asm("mov.b64 %0, {%1, %1};" : "=l"(d) : "f"(x));
    return d;
}
__device__ __forceinline__ float2 unpk(u64 a) {
    float2 r; asm("mov.b64 {%0, %1}, %2;" : "=f"(r.x), "=f"(r.y) : "l"(a));
    return r;
}
__device__ __forceinline__ u64 pk2(float x, float y) {
    u64 d; asm("mov.b64 %0, {%1, %2};" : "=l"(d) : "f"(x), "f"(y));
    return d;
}
__device__ __forceinline__ u64 relu2(u64 a) {
    float2 v = unpk(a);
    return pk2(fmaxf(v.x, 0.f), fmaxf(v.y, 0.f));
}
__device__ __forceinline__ void barpair(int id) {
    asm volatile("bar.sync %0, %1;" :: "r"(id), "r"(64) : "memory");
}

// fold-distribute over 32 slots: lane i ends with full-warp sum of v[i] in v[0]
__device__ __forceinline__ void fold32(float* v, int lane) {
    #pragma unroll
    for (int lvl = 0; lvl < 5; lvl++) {
        const int off = 16 >> lvl;
        #pragma unroll
        for (int m = 0; m < (16 >> lvl); m++) {
            float send = (lane & off) ? v[m] : v[m + off];
            float recv = __shfl_xor_sync(0xffffffffu, send, off);
            float keep = (lane & off) ? v[m + off] : v[m];
            v[m] = keep + recv;
        }
    }
}

__global__ void __launch_bounds__(THREADS, 4) visco_kernel(
    const float* __restrict__ e_,   const float* __restrict__ ed_,
    const float* __restrict__ E_,   const float* __restrict__ nu_,
    const float* __restrict__ We,   const float* __restrict__ be,
    const float* __restrict__ Wn,   const float* __restrict__ bn,
    const float* __restrict__ Wen1, const float* __restrict__ ben1,
    const float* __restrict__ Wen2, const float* __restrict__ ben2,
    const float* __restrict__ Wd1,  const float* __restrict__ bd1,
    const float* __restrict__ Wd2,  const float* __restrict__ bd2,
    float* __restrict__ out)
{
    extern __shared__ float sm[];
    float* W1s = sm + OFF_W1;

    const int tid  = threadIdx.x;
    const int lane = tid & 31;
    const int warp = tid >> 5;
    const int pairIdx = warp >> 1;     // 0,1
    const int pw      = warp & 1;      // warp-in-pair
    const int row0 = blockIdx.x * ROWS;

    float* xsP = sm + OFF_XS + pairIdx * 672;   // 2 buffers x 336
    float* pP  = sm + OFF_PP + pairIdx * 112;   // [2][56]

    // ---- cooperative smem fill: dynamic W1 rows 0..17 ----
    for (int i = tid; i < 18 * 512; i += THREADS) {
        int k = i >> 9, h = i & 511;
        W1s[i] = (h < 256) ? Wen1[k * 256 + h] : Wd1[k * 256 + (h - 256)];
    }

    // ---- rows 18..20: beta = We@W1mf, gamma = Wn@W1mf, alpha = bias fold ----
    // mf = [E*We+be, nu*Wn+bn]  =>  c[h] = alpha[h] + E*beta[h] + nu*gamma[h]
    {
        const int h0 = 4 * tid;
        const float* bsrc = (h0 < 256) ? (ben1 + h0) : (bd1 + h0 - 256);
        const float* Wb   = (h0 < 256) ? (Wen1 + 18 * 256 + h0)
                                       : (Wd1  + 18 * 256 + h0 - 256);
        float al[4], bt[4], gm[4];
        #pragma unroll
        for (int el = 0; el < 4; el++) { al[el] = bsrc[el]; bt[el] = 0.f; gm[el] = 0.f; }
        for (int i = 0; i < 16; i++) {
            float4 wa = *(const float4*)(Wb + i * 256);          // row 18+i (E-encoder)
            float4 wb = *(const float4*)(Wb + (16 + i) * 256);   // row 34+i (nu-encoder)
            float wev = We[i], bev = be[i], wnv = Wn[i], bnv = bn[i];
            bt[0] = fmaf(wev, wa.x, bt[0]); bt[1] = fmaf(wev, wa.y, bt[1]);
            bt[2] = fmaf(wev, wa.z, bt[2]); bt[3] = fmaf(wev, wa.w, bt[3]);
            gm[0] = fmaf(wnv, wb.x, gm[0]); gm[1] = fmaf(wnv, wb.y, gm[1]);
            gm[2] = fmaf(wnv, wb.z, gm[2]); gm[3] = fmaf(wnv, wb.w, gm[3]);
            al[0] = fmaf(bev, wa.x, al[0]); al[1] = fmaf(bev, wa.y, al[1]);
            al[2] = fmaf(bev, wa.z, al[2]); al[3] = fmaf(bev, wa.w, al[3]);
            al[0] = fmaf(bnv, wb.x, al[0]); al[1] = fmaf(bnv, wb.y, al[1]);
            al[2] = fmaf(bnv, wb.z, al[2]); al[3] = fmaf(bnv, wb.w, al[3]);
        }
        *(float4*)(W1s + 18 * 512 + h0) = make_float4(bt[0], bt[1], bt[2], bt[3]);
        *(float4*)(W1s + 19 * 512 + h0) = make_float4(gm[0], gm[1], gm[2], gm[3]);
        *(float4*)(W1s + 20 * 512 + h0) = make_float4(al[0], al[1], al[2], al[3]);
    }

    // ---- per-thread roles ----
    const int pt = pw * 32 + lane;            // thread index within pair (0..63)
    const int sj = pt % 6, sr = pt / 6;       // e/ed stagers (pt < 48)
    const bool stager = (pt < 48);
    const int ebase = (row0 + pairIdx * 8 + sr) * T_ * 6 + sj;

    // owners: lane < 28: slot s = pw*28 + lane; r = s/7, j = s%7
    const int s_own = pw * 28 + lane;
    const bool owner = (lane < 28);
    const int ro = s_own / 7, jo = s_own % 7;
    const int rowg = row0 + pairIdx * 8 + ro;
    const float bd2v  = (owner && jo < 6) ? bd2[jo] : 0.f;
    const float ben2r = ben2[0];
    float xi_val = 0.f;
    float* xi_ptr = out + B_ * T_ + (rowg * T_) * 6 + jo;   // jo<6 owners
    float* s_ptr  = out + rowg * T_;                        // jo==6 owners

    // ---- initial xs fill: e/ed(t=0), xi=0 (buffer 0); E/nu static (both buffers) ----
    if (stager) {
        *(u64*)(xsP + (sj * 8 + sr) * 2)        = dup2(e_[ebase]);
        *(u64*)(xsP + ((6 + sj) * 8 + sr) * 2)  = dup2(ed_[ebase]);
        *(u64*)(xsP + ((12 + sj) * 8 + sr) * 2) = 0ULL;
    }
    if (pt < 16) {
        int rr = pt & 7;
        int kk = 18 + (pt >> 3);
        float val = (pt < 8) ? E_[row0 + pairIdx * 8 + rr]
                             : nu_[row0 + pairIdx * 8 + rr];
        u64 d = dup2(val);
        *(u64*)(xsP + (kk * 8 + rr) * 2)       = d;
        *(u64*)(xsP + 336 + (kk * 8 + rr) * 2) = d;
    }

    // ---- layer-2 weights: straight from gmem into registers (one-time) ----
    const int h0l = 128 * pw + 4 * lane;
    ulonglong2 wen2x;
    {
        float4 w = *(const float4*)(Wen2 + h0l);
        wen2x.x = pk2(w.x, w.y); wen2x.y = pk2(w.z, w.w);
    }
    ulonglong2 wd2x[6];
    #pragma unroll
    for (int j = 0; j < 6; j++) {
        float a0 = Wd2[(h0l + 0) * 6 + j];
        float a1 = Wd2[(h0l + 1) * 6 + j];
        float a2 = Wd2[(h0l + 2) * 6 + j];
        float a3 = Wd2[(h0l + 3) * 6 + j];
        wd2x[j].x = pk2(a0, a1); wd2x[j].y = pk2(a2, a3);
    }
    __syncthreads();

    // ---- loop-invariant pointers ----
    const float* W1wE = W1s + 128 * pw + 4 * lane;          // + k*512
    const float* W1wK = W1s + 256 + 128 * pw + 4 * lane;    // + k*512

    const int barId = 1 + pairIdx;

    // prefetch e/ed for t=1
    float pe = 0.f, ped = 0.f;
    if (stager) { pe = e_[ebase + 6]; ped = ed_[ebase + 6]; }

    u64 u2[8][4];   // [row][energy0, energy1, kin0, kin1]

    // front half: alpha init + k in {0..11, 18, 19} from given buffer
    #define FRONT_HALF(XBUF)                                                  \
    {                                                                         \
        ulonglong2 aE = *(const ulonglong2*)(W1wE + 20 * 512);                \
        ulonglong2 aK = *(const ulonglong2*)(W1wK + 20 * 512);                \
        _Pragma("unroll")                                                     \
        for (int r = 0; r < 8; r++) {                                         \
            u2[r][0] = aE.x; u2[r][1] = aE.y;                                 \
            u2[r][2] = aK.x; u2[r][3] = aK.y;                                 \
        }                                                                     \
        _Pragma("unroll")                                                     \
        for (int ki = 0; ki < 14; ki++) {                                     \
            const int k = (ki < 12) ? ki : (ki + 6);                          \
            ulonglong2 wE = *(const ulonglong2*)(W1wE + k * 512);             \
            ulonglong2 wK = *(const ulonglong2*)(W1wK + k * 512);             \
            _Pragma("unroll")                                                 \
            for (int g = 0; g < 4; g++) {                                     \
                ulonglong2 xp = *(const ulonglong2*)((XBUF) + (k * 8 + 2 * g) * 2); \
                u2[2*g][0]   = ffma2(xp.x, wE.x, u2[2*g][0]);                 \
                u2[2*g][1]   = ffma2(xp.x, wE.y, u2[2*g][1]);                 \
                u2[2*g][2]   = ffma2(xp.x, wK.x, u2[2*g][2]);                 \
                u2[2*g][3]   = ffma2(xp.x, wK.y, u2[2*g][3]);                 \
                u2[2*g+1][0] = ffma2(xp.y, wE.x, u2[2*g+1][0]);               \
                u2[2*g+1][1] = ffma2(xp.y, wE.y, u2[2*g+1][1]);               \
                u2[2*g+1][2] = ffma2(xp.y, wK.x, u2[2*g+1][2]);               \
                u2[2*g+1][3] = ffma2(xp.y, wK.y, u2[2*g+1][3]);               \
            }                                                                 \
        }                                                                     \
    }

    // prologue: front half for t=0 from buffer 0
    FRONT_HALF(xsP)

    for (int t = 0; t < T_; t++) {
        const int p = t & 1;
        const float* xsp = xsP + p * 336;
        float* xsn = xsP + (p ^ 1) * 336;

        // ---- back half: xi inputs k=12..17 (xi(t) visible in xsp) ----
        #pragma unroll
        for (int k = 12; k < 18; k++) {
            ulonglong2 wE = *(const ulonglong2*)(W1wE + k * 512);
            ulonglong2 wK = *(const ulonglong2*)(W1wK + k * 512);
            #pragma unroll
            for (int g = 0; g < 4; g++) {
                ulonglong2 xp = *(const ulonglong2*)(xsp + (k * 8 + 2 * g) * 2);
                u2[2*g][0]   = ffma2(xp.x, wE.x, u2[2*g][0]);
                u2[2*g][1]   = ffma2(xp.x, wE.y, u2[2*g][1]);
                u2[2*g][2]   = ffma2(xp.x, wK.x, u2[2*g][2]);
                u2[2*g][3]   = ffma2(xp.x, wK.y, u2[2*g][3]);
                u2[2*g+1][0] = ffma2(xp.y, wE.x, u2[2*g+1][0]);
                u2[2*g+1][1] = ffma2(xp.y, wE.y, u2[2*g+1][1]);
                u2[2*g+1][2] = ffma2(xp.y, wK.x, u2[2*g+1][2]);
                u2[2*g+1][3] = ffma2(xp.y, wK.y, u2[2*g+1][3]);
            }
        }
        #pragma unroll
        for (int r = 0; r < 8; r++) {
            u2[r][0] = relu2(u2[r][0]); u2[r][1] = relu2(u2[r][1]);
            u2[r][2] = relu2(u2[r][2]); u2[r][3] = relu2(u2[r][3]);
        }

        // ---- layer-2 partials: two groups of 4 rows (28 slots each), fold, STS ----
        #pragma unroll
        for (int g2 = 0; g2 < 2; g2++) {
            float v[32];
            #pragma unroll
            for (int rr = 0; rr < 4; rr++) {
                const int r = 4 * g2 + rr;
                #pragma unroll
                for (int j = 0; j < 6; j++) {
                    u64 a2 = ffma2(u2[r][2], wd2x[j].x, 0ULL);
                    a2 = ffma2(u2[r][3], wd2x[j].y, a2);
                    float2 q = unpk(a2);
                    v[rr * 7 + j] = q.x + q.y;
                }
                u64 s2 = ffma2(u2[r][0], wen2x.x, 0ULL);
                s2 = ffma2(u2[r][1], wen2x.y, s2);
                float2 q = unpk(s2);
                v[rr * 7 + 6] = q.x + q.y;
            }
            #pragma unroll
            for (int m = 28; m < 32; m++) v[m] = 0.f;
            fold32(v, lane);
            if (lane < 28) pP[pw * 56 + g2 * 28 + lane] = v[0];
        }

        // stage e/ed(t+1) into next buffer; prefetch e/ed(t+2)
        if (stager) {
            *(u64*)(xsn + (sj * 8 + sr) * 2)       = dup2(pe);
            *(u64*)(xsn + ((6 + sj) * 8 + sr) * 2) = dup2(ped);
            int tn = (t + 2 < T_) ? (t + 2) : (T_ - 1);
            pe  = e_[ebase + tn * 6];
            ped = ed_[ebase + tn * 6];
        }
        barpair(barId);

        // ---- owner combine: outputs + Euler + xi(t+1) into next buffer ----
        if (owner) {
            float val = pP[s_own] + pP[56 + s_own];
            if (jo < 6) {
                xi_ptr[t * 6] = xi_val;                  // emit xi BEFORE update
                xi_val = fmaf(DT_, val + bd2v, xi_val);
                *(u64*)(xsn + ((12 + jo) * 8 + ro) * 2) = dup2(xi_val);
            } else {
                s_ptr[t] = val + ben2r;
            }
        }

        // ---- front half of t+1 (independent of xi(t+1)) ----
        FRONT_HALF(xsn)

        barpair(barId);   // xi(t+1) now visible for next iteration's back half
    }
    #undef FRONT_HALF
}

extern "C" void kernel_launch(void* const* d_in, const int* in_sizes, int n_in,
                              void* d_out, int out_size) {
    (void)in_sizes; (void)n_in; (void)out_size;
    cudaFuncSetAttribute(visco_kernel,
                         cudaFuncAttributeMaxDynamicSharedMemorySize, SMEM_BYTES);
    visco_kernel<<<NBLK, THREADS, SMEM_BYTES>>>(
        (const float*)d_in[0],  (const float*)d_in[1],
        (const float*)d_in[2],  (const float*)d_in[3],
        (const float*)d_in[4],  (const float*)d_in[5],
        (const float*)d_in[6],  (const float*)d_in[7],
        (const float*)d_in[8],  (const float*)d_in[9],
        (const float*)d_in[10], (const float*)d_in[11],
        (const float*)d_in[12], (const float*)d_in[13],
        (const float*)d_in[14], (const float*)d_in[15],
        (float*)d_out);
}

// round 10
// speedup vs baseline: 1.1945x; 1.1945x over previous
#include <cuda_runtime.h>

#define B_ 8192
#define T_ 128
#define DT_ 0.01f
#define WARPS 4
#define THREADS 128
#define ROWS_PER_BLOCK 16
#define NBLK (B_ / ROWS_PER_BLOCK)

// shared memory layout (float offsets)
// W1s rows: 0..17 dynamic (e6, ed6, xi6); 18 = beta (xE); 19 = gamma (xnu); 20 = alpha
#define OFF_W1   0        // [21][512]
#define OFF_WEN2 10752    // [256]
#define OFF_WD2T 11008    // [6][256] (transposed Wd2)
#define SMEM_FLOATS 12544
#define SMEM_BYTES (SMEM_FLOATS * 4)

typedef unsigned long long u64;

__device__ __forceinline__ u64 ffma2(u64 a, u64 b, u64 c) {
    u64 d; asm("fma.rn.f32x2 %0, %1, %2, %3;" : "=l"(d) : "l"(a), "l"(b), "l"(c));
    return d;
}
__device__ __forceinline__ u64 dup2(float x) {
    u64 d; asm("mov.b64 %0, {%1, %1};" : "=l"(d) : "f"(x));
    return d;
}
__device__ __forceinline__ float2 unpk(u64 a) {
    float2 r; asm("mov.b64 {%0, %1}, %2;" : "=f"(r.x), "=f"(r.y) : "l"(a));
    return r;
}
__device__ __forceinline__ u64 pk2(float x, float y) {
    u64 d; asm("mov.b64 %0, {%1, %2};" : "=l"(d) : "f"(x), "f"(y));
    return d;
}
__device__ __forceinline__ u64 relu2(u64 a) {
    float2 v = unpk(a);
    return pk2(fmaxf(v.x, 0.f), fmaxf(v.y, 0.f));
}

__global__ void __launch_bounds__(THREADS, 3) visco_kernel(
    const float* __restrict__ e_,   const float* __restrict__ ed_,
    const float* __restrict__ E_,   const float* __restrict__ nu_,
    const float* __restrict__ We,   const float* __restrict__ be,
    const float* __restrict__ Wn,   const float* __restrict__ bn,
    const float* __restrict__ Wen1, const float* __restrict__ ben1,
    const float* __restrict__ Wen2, const float* __restrict__ ben2,
    const float* __restrict__ Wd1,  const float* __restrict__ bd1,
    const float* __restrict__ Wd2,  const float* __restrict__ bd2,
    float* __restrict__ out)
{
    extern __shared__ float sm[];
    float* W1s   = sm + OFF_W1;
    float* Wen2s = sm + OFF_WEN2;
    float* Wd2t  = sm + OFF_WD2T;

    const int tid  = threadIdx.x;
    const int lane = tid & 31;
    const int warp = tid >> 5;

    // ---- cooperative smem fill: dynamic W1 rows 0..17 + layer-2 weights ----
    for (int i = tid; i < 18 * 512; i += THREADS) {
        int k = i >> 9, h = i & 511;
        W1s[i] = (h < 256) ? Wen1[k * 256 + h] : Wd1[k * 256 + (h - 256)];
    }
    for (int i = tid; i < 256; i += THREADS) Wen2s[i] = Wen2[i];
    for (int i = tid; i < 6 * 256; i += THREADS) {
        int j = i >> 8, h = i & 255;
        Wd2t[i] = Wd2[h * 6 + j];   // transpose -> conflict-free float4 reads
    }

    // ---- rows 18..20: beta = We@W1mf, gamma = Wn@W1mf, alpha = bias fold ----
    // mf = [E*We+be, nu*Wn+bn]  =>  c[h] = alpha[h] + E*beta[h] + nu*gamma[h]
    {
        const int h0 = 4 * tid;
        const float* bsrc = (h0 < 256) ? (ben1 + h0) : (bd1 + h0 - 256);
        const float* Wb   = (h0 < 256) ? (Wen1 + 18 * 256 + h0)
                                       : (Wd1  + 18 * 256 + h0 - 256);
        float al[4], bt[4], gm[4];
        #pragma unroll
        for (int el = 0; el < 4; el++) { al[el] = bsrc[el]; bt[el] = 0.f; gm[el] = 0.f; }
        for (int i = 0; i < 16; i++) {
            float4 wa = *(const float4*)(Wb + i * 256);          // W1 row 18+i (E-encoder)
            float4 wb = *(const float4*)(Wb + (16 + i) * 256);   // W1 row 34+i (nu-encoder)
            float wev = We[i], bev = be[i], wnv = Wn[i], bnv = bn[i];
            bt[0] = fmaf(wev, wa.x, bt[0]); bt[1] = fmaf(wev, wa.y, bt[1]);
            bt[2] = fmaf(wev, wa.z, bt[2]); bt[3] = fmaf(wev, wa.w, bt[3]);
            gm[0] = fmaf(wnv, wb.x, gm[0]); gm[1] = fmaf(wnv, wb.y, gm[1]);
            gm[2] = fmaf(wnv, wb.z, gm[2]); gm[3] = fmaf(wnv, wb.w, gm[3]);
            al[0] = fmaf(bev, wa.x, al[0]); al[1] = fmaf(bev, wa.y, al[1]);
            al[2] = fmaf(bev, wa.z, al[2]); al[3] = fmaf(bev, wa.w, al[3]);
            al[0] = fmaf(bnv, wb.x, al[0]); al[1] = fmaf(bnv, wb.y, al[1]);
            al[2] = fmaf(bnv, wb.z, al[2]); al[3] = fmaf(bnv, wb.w, al[3]);
        }
        *(float4*)(W1s + 18 * 512 + h0) = make_float4(bt[0], bt[1], bt[2], bt[3]);
        *(float4*)(W1s + 19 * 512 + h0) = make_float4(gm[0], gm[1], gm[2], gm[3]);
        *(float4*)(W1s + 20 * 512 + h0) = make_float4(al[0], al[1], al[2], al[3]);
    }

    const int gw   = blockIdx.x * WARPS + warp;
    const int row0 = gw * 4;

    // per-row E/nu kept in registers (broadcast-cached LDG)
    u64 Ed[4], nud[4];
    #pragma unroll
    for (int r = 0; r < 4; r++) {
        Ed[r]  = dup2(E_[row0 + r]);
        nud[r] = dup2(nu_[row0 + r]);
    }

    // ---- distributed state: lane i = r*8+j owns output slot (r, j) ----
    // j in [0,6): xi component j of row r.  j == 6: stress of row r.  j == 7: dummy.
    const int jown = lane & 7;
    const int rown = lane >> 3;
    const float bd2v  = (jown < 6) ? bd2[jown] : 0.f;
    const float ben2r = ben2[0];
    float xi_val = 0.f;

    float* xi_ptr = out + B_ * T_ + ((row0 + rown) * T_) * 6 + jown;   // + t*6
    float* s_ptr  = out + (row0 + rown) * T_;                          // + t

    // lane -> (rowpair, input-dim) mapping for the per-step e/edot gather
    const int l2  = lane & 15;
    const bool ldp = (l2 < 12);
    const float* lsrc = (l2 < 6) ? e_ : ed_;
    const int d_l = (l2 < 6) ? l2 : (l2 - 6);
    const int rA = row0 + ((lane < 16) ? 0 : 1);   // source rows for ld0
    const int rB = row0 + ((lane < 16) ? 2 : 3);   // source rows for ld1
    const int base0 = rA * T_ * 6 + d_l;
    const int base1 = rB * T_ * 6 + d_l;

    const float* W1w   = W1s + 4 * lane;            // + k*512 + 128*q
    const float* wen2w = Wen2s + 4 * lane;          // + 128*q
    const float* wd2w  = Wd2t + 4 * lane;           // + j*256 + 128*q

    __syncthreads();

    float nxt0 = 0.f, nxt1 = 0.f;
    if (ldp) { nxt0 = lsrc[base0]; nxt1 = lsrc[base1]; }

    for (int t = 0; t < T_; t++) {
        const float ld0 = nxt0, ld1 = nxt1;
        {
            int tn = (t + 1 < T_) ? (t + 1) : (T_ - 1);
            if (ldp) { nxt0 = lsrc[base0 + tn * 6]; nxt1 = lsrc[base1 + tn * 6]; }
        }

        // ---- init accumulators from shared alpha row (broadcast across rows) ----
        u64 u2[4][4][2];   // [row][q][pair]
        #pragma unroll
        for (int q = 0; q < 4; q++) {
            ulonglong2 a = *(const ulonglong2*)(W1w + 20 * 512 + 128 * q);
            #pragma unroll
            for (int r = 0; r < 4; r++) { u2[r][q][0] = a.x; u2[r][q][1] = a.y; }
        }

        // ---- layer 1: 20 inputs x 512 hidden (W1 smem loads shared by 4 rows) ----
        #pragma unroll
        for (int k = 0; k < 20; k++) {
            u64 xd[4];
            if (k < 12) {
                xd[0] = dup2(__shfl_sync(0xffffffffu, ld0, k));
                xd[1] = dup2(__shfl_sync(0xffffffffu, ld0, 16 + k));
                xd[2] = dup2(__shfl_sync(0xffffffffu, ld1, k));
                xd[3] = dup2(__shfl_sync(0xffffffffu, ld1, 16 + k));
            } else if (k < 18) {
                // xi[r][k-12] lives in lane r*8 + (k-12)
                const int js = k - 12;
                xd[0] = dup2(__shfl_sync(0xffffffffu, xi_val, 0 * 8 + js));
                xd[1] = dup2(__shfl_sync(0xffffffffu, xi_val, 1 * 8 + js));
                xd[2] = dup2(__shfl_sync(0xffffffffu, xi_val, 2 * 8 + js));
                xd[3] = dup2(__shfl_sync(0xffffffffu, xi_val, 3 * 8 + js));
            } else if (k == 18) {
                xd[0] = Ed[0]; xd[1] = Ed[1]; xd[2] = Ed[2]; xd[3] = Ed[3];
            } else {
                xd[0] = nud[0]; xd[1] = nud[1]; xd[2] = nud[2]; xd[3] = nud[3];
            }
            #pragma unroll
            for (int q = 0; q < 4; q++) {
                ulonglong2 w = *(const ulonglong2*)(W1w + k * 512 + 128 * q);
                #pragma unroll
                for (int r = 0; r < 4; r++) {
                    u2[r][q][0] = ffma2(xd[r], w.x, u2[r][q][0]);
                    u2[r][q][1] = ffma2(xd[r], w.y, u2[r][q][1]);
                }
            }
        }

        // relu
        #pragma unroll
        for (int q = 0; q < 4; q++)
            #pragma unroll
            for (int r = 0; r < 4; r++) {
                u2[r][q][0] = relu2(u2[r][q][0]);
                u2[r][q][1] = relu2(u2[r][q][1]);
            }

        // ---- layer-2 local partials into slot array v[32]; slot i = r*8+j ----
        float v[32];
        // kinetics (q=2,3): j outer so weight loads stay transient
        #pragma unroll
        for (int j = 0; j < 6; j++) {
            ulonglong2 w0 = *(const ulonglong2*)(wd2w + j * 256);
            ulonglong2 w1 = *(const ulonglong2*)(wd2w + j * 256 + 128);
            #pragma unroll
            for (int r = 0; r < 4; r++) {
                u64 a2 = ffma2(u2[r][2][0], w0.x, 0ULL);
                a2 = ffma2(u2[r][2][1], w0.y, a2);
                a2 = ffma2(u2[r][3][0], w1.x, a2);
                a2 = ffma2(u2[r][3][1], w1.y, a2);
                float2 q = unpk(a2);
                v[r * 8 + j] = q.x + q.y;
            }
        }
        // stress (q=0,1)
        {
            ulonglong2 w0 = *(const ulonglong2*)(wen2w);
            ulonglong2 w1 = *(const ulonglong2*)(wen2w + 128);
            #pragma unroll
            for (int r = 0; r < 4; r++) {
                u64 s2 = ffma2(u2[r][0][0], w0.x, 0ULL);
                s2 = ffma2(u2[r][0][1], w0.y, s2);
                s2 = ffma2(u2[r][1][0], w1.x, s2);
                s2 = ffma2(u2[r][1][1], w1.y, s2);
                float2 q = unpk(s2);
                v[r * 8 + 6] = q.x + q.y;
                v[r * 8 + 7] = 0.f;
            }
        }

        // ---- fold-distribute reduction: lane i ends with sum over lanes of v[i] ----
        #pragma unroll
        for (int lvl = 0; lvl < 5; lvl++) {
            const int off = 16 >> lvl;
            #pragma unroll
            for (int m = 0; m < (16 >> lvl); m++) {
                float send = (lane & off) ? v[m] : v[m + off];
                float recv = __shfl_xor_sync(0xffffffffu, send, off);
                float keep = (lane & off) ? v[m + off] : v[m];
                v[m] = keep + recv;
            }
        }
        // v[0] now holds this lane's owned slot value

        // ---- outputs: xi BEFORE update (owner lanes j<6), stress (j==6) ----
        if (jown < 6)       xi_ptr[t * 6] = xi_val;
        else if (jown == 6) s_ptr[t] = v[0] + ben2r;

        // explicit Euler update (garbage on non-owner lanes, never read)
        xi_val = fmaf(DT_, v[0] + bd2v, xi_val);
    }
}

extern "C" void kernel_launch(void* const* d_in, const int* in_sizes, int n_in,
                              void* d_out, int out_size) {
    (void)in_sizes; (void)n_in; (void)out_size;
    cudaFuncSetAttribute(visco_kernel,
                         cudaFuncAttributeMaxDynamicSharedMemorySize, SMEM_BYTES);
    visco_kernel<<<NBLK, THREADS, SMEM_BYTES>>>(
        (const float*)d_in[0],  (const float*)d_in[1],
        (const float*)d_in[2],  (const float*)d_in[3],
        (const float*)d_in[4],  (const float*)d_in[5],
        (const float*)d_in[6],  (const float*)d_in[7],
        (const float*)d_in[8],  (const float*)d_in[9],
        (const float*)d_in[10], (const float*)d_in[11],
        (const float*)d_in[12], (const float*)d_in[13],
        (const float*)d_in[14], (const float*)d_in[15],
        (float*)d_out);
}